// round 13
// baseline (speedup 1.0000x reference)
#include <cuda_runtime.h>
#include <cuda_fp16.h>
#include <cstdint>

#define MTOT  16384
#define KDIM  1024
#define NDIM  4096

#define BM 128
#define BN 256
#define BK 32
#define KITERS (KDIM / BK)     // 32
#define NSTAGE 4
#define STG 24576              // Ah 8K | Bh 16K
#define AH_OFF 0
#define BH_OFF 8192
#define DYN_SMEM (NSTAGE * STG)   // 96 KB -> 1 CTA/SM
#define GROUP_M 16

// ---------------- scratch (device globals — allowed) ----------------
__device__ __half g_Xh[(size_t)MTOT * KDIM];    // 32MB
__device__ __half g_Wh[2ull * NDIM * KDIM];     // 16MB (transposed [e][n][k])
__device__ int g_rows[2 * MTOT];                // compacted row lists
__device__ int g_cnt[2];                        // per-expert counts

// ---------------- helpers ----------------
__device__ __forceinline__ uint32_t smem_u32(const void* p) {
    uint32_t a;
    asm("{ .reg .u64 t; cvta.to.shared.u64 t, %1; cvt.u32.u64 %0, t; }" : "=r"(a) : "l"(p));
    return a;
}
__device__ __forceinline__ void cp16(uint32_t s, const void* g) {
    asm volatile("cp.async.cg.shared.global [%0], [%1], 16;\n" :: "r"(s), "l"(g));
}
__device__ __forceinline__ void ldsm4(uint32_t& r0, uint32_t& r1, uint32_t& r2, uint32_t& r3,
                                      uint32_t addr) {
    asm volatile("ldmatrix.sync.aligned.m8n8.x4.shared.b16 {%0,%1,%2,%3}, [%4];"
                 : "=r"(r0), "=r"(r1), "=r"(r2), "=r"(r3) : "r"(addr));
}
__device__ __forceinline__ void mma16816(float* c, const uint32_t* a, const uint32_t* b) {
    asm volatile(
        "mma.sync.aligned.m16n8k16.row.col.f32.f16.f16.f32 "
        "{%0,%1,%2,%3}, {%4,%5,%6,%7}, {%8,%9}, {%0,%1,%2,%3};"
        : "+f"(c[0]), "+f"(c[1]), "+f"(c[2]), "+f"(c[3])
        : "r"(a[0]), "r"(a[1]), "r"(a[2]), "r"(a[3]), "r"(b[0]), "r"(b[1]));
}

// ---------------- prologue kernels ----------------
__global__ void zero_cnt_kernel() {
    if (threadIdx.x < 2) g_cnt[threadIdx.x] = 0;
}

__global__ void build_lists_kernel(const int* __restrict__ types) {
    int r = blockIdx.x * 256 + threadIdx.x;
    int e = types[r] ? 1 : 0;            // clamp to {0,1}
    int slot = atomicAdd(&g_cnt[e], 1);
    g_rows[e * MTOT + slot] = r;
}

__global__ __launch_bounds__(256) void convert_x_kernel(const float* __restrict__ X) {
    size_t i = (size_t)blockIdx.x * 256 + threadIdx.x;   // float4 index
    float4 v = reinterpret_cast<const float4*>(X)[i];
    uint2 hp;
    hp.x = (uint32_t)__half_as_ushort(__float2half_rn(v.x)) |
           ((uint32_t)__half_as_ushort(__float2half_rn(v.y)) << 16);
    hp.y = (uint32_t)__half_as_ushort(__float2half_rn(v.z)) |
           ((uint32_t)__half_as_ushort(__float2half_rn(v.w)) << 16);
    reinterpret_cast<uint2*>(g_Xh)[i] = hp;
}

__global__ __launch_bounds__(256) void convert_w_kernel(const float* __restrict__ W0,
                                                        const float* __restrict__ W1) {
    const float* __restrict__ W = blockIdx.z ? W1 : W0;
    __shared__ float t[32][33];
    int n0 = blockIdx.x * 32, k0 = blockIdx.y * 32;
    int tx = threadIdx.x, ty = threadIdx.y;  // 32 x 8
    #pragma unroll
    for (int j = 0; j < 4; j++)
        t[ty + j * 8][tx] = W[(size_t)(k0 + ty + j * 8) * NDIM + n0 + tx];
    __syncthreads();
    size_t base = (size_t)blockIdx.z * NDIM * KDIM;
    #pragma unroll
    for (int j = 0; j < 4; j++) {
        float v = t[tx][ty + j * 8];
        size_t idx = base + (size_t)(n0 + ty + j * 8) * KDIM + k0 + tx;
        g_Wh[idx] = __float2half_rn(v);
    }
}

// ---------------- main GEMM: 128x256 tile, gathered rows, fp16 mma.sync ----------------
__global__ __launch_bounds__(256, 1) void mot_gemm_mma(
    const float* __restrict__ b0,
    const float* __restrict__ b1,
    float* __restrict__ out)
{
    extern __shared__ char dyn[];
    __shared__ int rows_s[BM];
    const uint32_t base = smem_u32(dyn);

    const int expert = blockIdx.z;
    const int count = g_cnt[expert];

    const int nNB = NDIM / BN;   // 16
    const int bid = blockIdx.x;
    const int group = bid / (GROUP_M * nNB);
    const int within = bid % (GROUP_M * nNB);
    const int mb = group * GROUP_M + (within % GROUP_M);
    const int nb = within / GROUP_M;
    const int m0 = mb * BM;      // slot offset into compacted list
    const int n0 = nb * BN;

    if (m0 >= count) return;     // tile fully beyond routed rows (uniform)

    const int tid = threadIdx.x;
    const int lane = tid & 31;
    const int wid = tid >> 5;
    const int wm = wid & 1;      // 2 warps along M (64 rows each)
    const int wn = wid >> 1;     // 4 warps along N (64 cols each)
    const int wm0 = wm * 64;
    const int wn0 = wn * 64;

    if (tid < BM) rows_s[tid] = g_rows[expert * MTOT + m0 + tid];
    __syncthreads();

    const size_t wbase = (size_t)expert * NDIM * KDIM;

    // per-thread gather pointers (advance by BK each stage)
    const int lrow0 = tid >> 2;            // 0..63
    const int lrow1 = lrow0 + 64;          // 64..127
    const int ch = tid & 3;
    const __half* pa0 = g_Xh + (size_t)rows_s[lrow0] * KDIM + ch * 8;
    const __half* pa1 = g_Xh + (size_t)rows_s[lrow1] * KDIM + ch * 8;
    // B: 256 rows, 4 per thread (lrow0 + 64j)
    const __half* pb0 = g_Wh + wbase + (size_t)(n0 + lrow0) * KDIM + ch * 8;
    const __half* pb1 = pb0 + (size_t)64 * KDIM;
    const __half* pb2 = pb0 + (size_t)128 * KDIM;
    const __half* pb3 = pb0 + (size_t)192 * KDIM;
    const uint32_t soff0 = lrow0 * 64 + (((ch ^ (lrow0 & 3))) << 4);
    const uint32_t soff1 = lrow1 * 64 + (((ch ^ (lrow1 & 3))) << 4);

    auto load_stage = [&](uint32_t sb) {
        cp16(sb + AH_OFF + soff0, pa0);
        cp16(sb + AH_OFF + soff1, pa1);
        cp16(sb + BH_OFF + soff0, pb0);
        cp16(sb + BH_OFF + soff0 + 4096, pb1);
        cp16(sb + BH_OFF + soff0 + 8192, pb2);
        cp16(sb + BH_OFF + soff0 + 12288, pb3);
        pa0 += BK; pa1 += BK; pb0 += BK; pb1 += BK; pb2 += BK; pb3 += BK;
    };

    // prefill 3 stages
    load_stage(base + 0 * STG);
    asm volatile("cp.async.commit_group;" ::: "memory");
    load_stage(base + 1 * STG);
    asm volatile("cp.async.commit_group;" ::: "memory");
    load_stage(base + 2 * STG);
    asm volatile("cp.async.commit_group;" ::: "memory");

    const int q = lane >> 3, r = lane & 7;
    const int arow = wm0 + (q & 1) * 8 + r;
    const int apar = q >> 1;
    const int aswz = arow & 3;
    const int brow = wn0 + ((q >> 1) & 1) * 8 + r;
    const int bpar = q & 1;
    const int bswz = brow & 3;

    float acc[4][8][4];
    #pragma unroll
    for (int i = 0; i < 4; i++)
        #pragma unroll
        for (int j = 0; j < 8; j++)
            #pragma unroll
            for (int v = 0; v < 4; v++)
                acc[i][j][v] = 0.0f;

    for (int kt = 0; kt < KITERS; ++kt) {
        asm volatile("cp.async.wait_group 2;" ::: "memory");
        __syncthreads();

        if (kt + 3 < KITERS)
            load_stage(base + ((kt + 3) & (NSTAGE - 1)) * STG);
        asm volatile("cp.async.commit_group;" ::: "memory");

        uint32_t sb = base + (kt & (NSTAGE - 1)) * STG;
        #pragma unroll
        for (int ks = 0; ks < 2; ks++) {
            uint32_t ah[4][4], bh[8][2];
            const uint32_t achunk = ((uint32_t)(ks * 2 + apar) ^ aswz) << 4;
            const uint32_t bchunk = ((uint32_t)(ks * 2 + bpar) ^ bswz) << 4;
            #pragma unroll
            for (int mt = 0; mt < 4; mt++) {
                uint32_t ra = (arow + mt * 16) * 64 + achunk;
                ldsm4(ah[mt][0], ah[mt][1], ah[mt][2], ah[mt][3], sb + AH_OFF + ra);
            }
            #pragma unroll
            for (int p = 0; p < 4; p++) {
                uint32_t rb = (brow + p * 16) * 64 + bchunk;
                ldsm4(bh[2 * p][0], bh[2 * p][1], bh[2 * p + 1][0], bh[2 * p + 1][1],
                      sb + BH_OFF + rb);
            }
            #pragma unroll
            for (int mt = 0; mt < 4; mt++)
                #pragma unroll
                for (int nt = 0; nt < 8; nt++)
                    mma16816(acc[mt][nt], ah[mt], bh[nt]);
        }
    }
    asm volatile("cp.async.wait_group 0;" ::: "memory");

    // ---------------- epilogue ----------------
    // Row slot is genuinely routed to `expert` (no mask). Write y+bias to this
    // expert's slab, zeros to the other slab (covers every row exactly once).
    const float* __restrict__ bias = expert ? b1 : b0;

    const size_t slab = (size_t)MTOT * NDIM;
    float* oY = out + (size_t)expert * slab;        // computed slab
    float* oZ = out + (size_t)(1 - expert) * slab;  // zero slab

    #pragma unroll
    for (int mt = 0; mt < 4; mt++) {
        int slot0 = wm0 + mt * 16 + (lane >> 2);
        int slot1 = slot0 + 8;
        bool v0 = (m0 + slot0) < count;
        bool v1 = (m0 + slot1) < count;
        int r0 = rows_s[slot0];
        int r1 = rows_s[slot1];
        #pragma unroll
        for (int nt = 0; nt < 8; nt++) {
            int col = n0 + wn0 + nt * 8 + (lane & 3) * 2;
            float bx = __ldg(&bias[col]);
            float by = __ldg(&bias[col + 1]);
            if (v0) {
                float2 y;
                y.x = acc[mt][nt][0] + bx;
                y.y = acc[mt][nt][1] + by;
                *reinterpret_cast<float2*>(oY + (size_t)r0 * NDIM + col) = y;
                *reinterpret_cast<float2*>(oZ + (size_t)r0 * NDIM + col) =
                    make_float2(0.0f, 0.0f);
            }
            if (v1) {
                float2 y;
                y.x = acc[mt][nt][2] + bx;
                y.y = acc[mt][nt][3] + by;
                *reinterpret_cast<float2*>(oY + (size_t)r1 * NDIM + col) = y;
                *reinterpret_cast<float2*>(oZ + (size_t)r1 * NDIM + col) =
                    make_float2(0.0f, 0.0f);
            }
        }
    }
}

extern "C" void kernel_launch(void* const* d_in, const int* in_sizes, int n_in,
                              void* d_out, int out_size) {
    const float* X     = (const float*)d_in[0];
    const int*   types = (const int*)  d_in[1];
    const float* W0    = (const float*)d_in[2];
    const float* b0    = (const float*)d_in[3];
    const float* W1    = (const float*)d_in[4];
    const float* b1    = (const float*)d_in[5];
    float* out = (float*)d_out;

    zero_cnt_kernel<<<1, 32>>>();
    build_lists_kernel<<<MTOT / 256, 256>>>(types);
    convert_x_kernel<<<(MTOT * KDIM / 4) / 256, 256>>>(X);
    {
        dim3 g(NDIM / 32, KDIM / 32, 2);
        dim3 b(32, 8);
        convert_w_kernel<<<g, b>>>(W0, W1);
    }

    cudaFuncSetAttribute(mot_gemm_mma, cudaFuncAttributeMaxDynamicSharedMemorySize, DYN_SMEM);
    dim3 grid((MTOT / BM) * (NDIM / BN), 1, 2);   // worst-case grid; tiles early-exit
    mot_gemm_mma<<<grid, 256, DYN_SMEM>>>(b0, b1, out);
}

// round 14
// speedup vs baseline: 1.0661x; 1.0661x over previous
#include <cuda_runtime.h>
#include <cuda_fp16.h>
#include <cstdint>

#define MTOT  16384
#define KDIM  1024
#define NDIM  4096

#define BM 128
#define BN 128
#define BK 32
#define KITERS (KDIM / BK)     // 32
#define NSTAGE 4
#define STG 16384              // Ah 8K | Bh 8K
#define AH_OFF 0
#define BH_OFF 8192
#define DYN_SMEM (NSTAGE * STG)   // 64 KB -> 2 CTAs/SM
#define GROUP_M 16

// ---------------- scratch (device globals — allowed) ----------------
__device__ __half g_Xh[(size_t)MTOT * KDIM];    // 32MB
__device__ __half g_Wh[2ull * NDIM * KDIM];     // 16MB (transposed [e][n][k])
__device__ int g_rows[2 * MTOT];                // compacted row lists
__device__ int g_cnt[2];                        // per-expert counts

// ---------------- helpers ----------------
__device__ __forceinline__ uint32_t smem_u32(const void* p) {
    uint32_t a;
    asm("{ .reg .u64 t; cvta.to.shared.u64 t, %1; cvt.u32.u64 %0, t; }" : "=r"(a) : "l"(p));
    return a;
}
__device__ __forceinline__ void cp16(uint32_t s, const void* g) {
    asm volatile("cp.async.cg.shared.global [%0], [%1], 16;\n" :: "r"(s), "l"(g));
}
__device__ __forceinline__ void ldsm4(uint32_t& r0, uint32_t& r1, uint32_t& r2, uint32_t& r3,
                                      uint32_t addr) {
    asm volatile("ldmatrix.sync.aligned.m8n8.x4.shared.b16 {%0,%1,%2,%3}, [%4];"
                 : "=r"(r0), "=r"(r1), "=r"(r2), "=r"(r3) : "r"(addr));
}
__device__ __forceinline__ void mma16816(float* c, const uint32_t* a, const uint32_t* b) {
    asm volatile(
        "mma.sync.aligned.m16n8k16.row.col.f32.f16.f16.f32 "
        "{%0,%1,%2,%3}, {%4,%5,%6,%7}, {%8,%9}, {%0,%1,%2,%3};"
        : "+f"(c[0]), "+f"(c[1]), "+f"(c[2]), "+f"(c[3])
        : "r"(a[0]), "r"(a[1]), "r"(a[2]), "r"(a[3]), "r"(b[0]), "r"(b[1]));
}

// ---------------- prologue kernels ----------------
// convert_x also zeroes the per-expert counters; kernel-boundary ordering on the
// stream guarantees the zeroing completes before build_lists' atomics start.
__global__ __launch_bounds__(256) void convert_x_kernel(const float* __restrict__ X) {
    if (blockIdx.x == 0 && threadIdx.x < 2) g_cnt[threadIdx.x] = 0;
    size_t i = (size_t)blockIdx.x * 256 + threadIdx.x;   // float4 index
    float4 v = reinterpret_cast<const float4*>(X)[i];
    uint2 hp;
    hp.x = (uint32_t)__half_as_ushort(__float2half_rn(v.x)) |
           ((uint32_t)__half_as_ushort(__float2half_rn(v.y)) << 16);
    hp.y = (uint32_t)__half_as_ushort(__float2half_rn(v.z)) |
           ((uint32_t)__half_as_ushort(__float2half_rn(v.w)) << 16);
    reinterpret_cast<uint2*>(g_Xh)[i] = hp;
}

__global__ void build_lists_kernel(const int* __restrict__ types) {
    int r = blockIdx.x * 256 + threadIdx.x;
    int e = types[r] ? 1 : 0;            // clamp to {0,1}
    int slot = atomicAdd(&g_cnt[e], 1);
    g_rows[e * MTOT + slot] = r;
}

__global__ __launch_bounds__(256) void convert_w_kernel(const float* __restrict__ W0,
                                                        const float* __restrict__ W1) {
    const float* __restrict__ W = blockIdx.z ? W1 : W0;
    __shared__ float t[32][33];
    int n0 = blockIdx.x * 32, k0 = blockIdx.y * 32;
    int tx = threadIdx.x, ty = threadIdx.y;  // 32 x 8
    #pragma unroll
    for (int j = 0; j < 4; j++)
        t[ty + j * 8][tx] = W[(size_t)(k0 + ty + j * 8) * NDIM + n0 + tx];
    __syncthreads();
    size_t base = (size_t)blockIdx.z * NDIM * KDIM;
    #pragma unroll
    for (int j = 0; j < 4; j++) {
        float v = t[tx][ty + j * 8];
        size_t idx = base + (size_t)(n0 + ty + j * 8) * KDIM + k0 + tx;
        g_Wh[idx] = __float2half_rn(v);
    }
}

// ---------------- main GEMM: gathered rows, plain fp16 mma.sync ----------------
__global__ __launch_bounds__(256, 2) void mot_gemm_mma(
    const float* __restrict__ b0,
    const float* __restrict__ b1,
    float* __restrict__ out)
{
    extern __shared__ char dyn[];
    __shared__ int rows_s[BM];
    const uint32_t base = smem_u32(dyn);

    const int expert = blockIdx.z;
    const int count = g_cnt[expert];

    const int nNB = NDIM / BN;   // 32
    const int bid = blockIdx.x;
    const int group = bid / (GROUP_M * nNB);
    const int within = bid % (GROUP_M * nNB);
    const int mb = group * GROUP_M + (within % GROUP_M);
    const int nb = within / GROUP_M;
    const int m0 = mb * BM;      // slot offset into compacted list
    const int n0 = nb * BN;

    if (m0 >= count) return;     // tile fully beyond routed rows (uniform)

    const int tid = threadIdx.x;
    const int lane = tid & 31;
    const int wid = tid >> 5;
    const int wm = wid & 1;
    const int wn = wid >> 1;
    const int wm0 = wm * 64;
    const int wn0 = wn * 32;

    if (tid < BM) rows_s[tid] = g_rows[expert * MTOT + m0 + tid];
    __syncthreads();

    const size_t wbase = (size_t)expert * NDIM * KDIM;

    // per-thread gather pointers (advance by BK each stage)
    const int lrow0 = tid >> 2;            // 0..63
    const int lrow1 = lrow0 + 64;          // 64..127
    const int ch = tid & 3;
    const __half* pa0 = g_Xh + (size_t)rows_s[lrow0] * KDIM + ch * 8;
    const __half* pa1 = g_Xh + (size_t)rows_s[lrow1] * KDIM + ch * 8;
    const __half* pb0 = g_Wh + wbase + (size_t)(n0 + lrow0) * KDIM + ch * 8;
    const __half* pb1 = g_Wh + wbase + (size_t)(n0 + lrow1) * KDIM + ch * 8;
    const uint32_t soff0 = lrow0 * 64 + (((ch ^ (lrow0 & 3))) << 4);
    const uint32_t soff1 = lrow1 * 64 + (((ch ^ (lrow1 & 3))) << 4);

    auto load_stage = [&](uint32_t sb) {
        cp16(sb + AH_OFF + soff0, pa0);
        cp16(sb + AH_OFF + soff1, pa1);
        cp16(sb + BH_OFF + soff0, pb0);
        cp16(sb + BH_OFF + soff1, pb1);
        pa0 += BK; pa1 += BK; pb0 += BK; pb1 += BK;
    };

    // prefill 3 stages
    load_stage(base + 0 * STG);
    asm volatile("cp.async.commit_group;" ::: "memory");
    load_stage(base + 1 * STG);
    asm volatile("cp.async.commit_group;" ::: "memory");
    load_stage(base + 2 * STG);
    asm volatile("cp.async.commit_group;" ::: "memory");

    const int q = lane >> 3, r = lane & 7;
    const int arow = wm0 + (q & 1) * 8 + r;
    const int apar = q >> 1;
    const int aswz = arow & 3;
    const int brow = wn0 + ((q >> 1) & 1) * 8 + r;
    const int bpar = q & 1;
    const int bswz = brow & 3;

    float acc[4][4][4];
    #pragma unroll
    for (int i = 0; i < 4; i++)
        #pragma unroll
        for (int j = 0; j < 4; j++)
            #pragma unroll
            for (int v = 0; v < 4; v++)
                acc[i][j][v] = 0.0f;

    #pragma unroll 4
    for (int kt = 0; kt < KITERS; ++kt) {
        asm volatile("cp.async.wait_group 2;" ::: "memory");
        __syncthreads();

        if (kt + 3 < KITERS)
            load_stage(base + ((kt + 3) & (NSTAGE - 1)) * STG);
        asm volatile("cp.async.commit_group;" ::: "memory");

        uint32_t sb = base + (kt & (NSTAGE - 1)) * STG;
        #pragma unroll
        for (int ks = 0; ks < 2; ks++) {
            uint32_t ah[4][4], bh[4][2];
            const uint32_t achunk = ((uint32_t)(ks * 2 + apar) ^ aswz) << 4;
            const uint32_t bchunk = ((uint32_t)(ks * 2 + bpar) ^ bswz) << 4;
            #pragma unroll
            for (int mt = 0; mt < 4; mt++) {
                uint32_t ra = (arow + mt * 16) * 64 + achunk;
                ldsm4(ah[mt][0], ah[mt][1], ah[mt][2], ah[mt][3], sb + AH_OFF + ra);
            }
            #pragma unroll
            for (int p = 0; p < 2; p++) {
                uint32_t rb = (brow + p * 16) * 64 + bchunk;
                ldsm4(bh[2 * p][0], bh[2 * p][1], bh[2 * p + 1][0], bh[2 * p + 1][1],
                      sb + BH_OFF + rb);
            }
            #pragma unroll
            for (int mt = 0; mt < 4; mt++)
                #pragma unroll
                for (int nt = 0; nt < 4; nt++)
                    mma16816(acc[mt][nt], ah[mt], bh[nt]);
        }
    }
    asm volatile("cp.async.wait_group 0;" ::: "memory");

    // ---------------- epilogue ----------------
    // Row slot is genuinely routed to `expert` (no mask). Write y+bias to this
    // expert's slab, zeros to the other slab (covers every row exactly once).
    const float* __restrict__ bias = expert ? b1 : b0;
    float bv[4][2];
    #pragma unroll
    for (int nt = 0; nt < 4; nt++) {
        int col = n0 + wn0 + nt * 8 + (lane & 3) * 2;
        bv[nt][0] = __ldg(&bias[col]);
        bv[nt][1] = __ldg(&bias[col + 1]);
    }

    const size_t slab = (size_t)MTOT * NDIM;
    float* oY = out + (size_t)expert * slab;        // computed slab
    float* oZ = out + (size_t)(1 - expert) * slab;  // zero slab

    #pragma unroll
    for (int mt = 0; mt < 4; mt++) {
        int slot0 = wm0 + mt * 16 + (lane >> 2);
        int slot1 = slot0 + 8;
        bool v0 = (m0 + slot0) < count;
        bool v1 = (m0 + slot1) < count;
        int r0 = rows_s[slot0];
        int r1 = rows_s[slot1];
        #pragma unroll
        for (int nt = 0; nt < 4; nt++) {
            int col = n0 + wn0 + nt * 8 + (lane & 3) * 2;
            if (v0) {
                float2 y;
                y.x = acc[mt][nt][0] + bv[nt][0];
                y.y = acc[mt][nt][1] + bv[nt][1];
                *reinterpret_cast<float2*>(oY + (size_t)r0 * NDIM + col) = y;
                *reinterpret_cast<float2*>(oZ + (size_t)r0 * NDIM + col) =
                    make_float2(0.0f, 0.0f);
            }
            if (v1) {
                float2 y;
                y.x = acc[mt][nt][2] + bv[nt][0];
                y.y = acc[mt][nt][3] + bv[nt][1];
                *reinterpret_cast<float2*>(oY + (size_t)r1 * NDIM + col) = y;
                *reinterpret_cast<float2*>(oZ + (size_t)r1 * NDIM + col) =
                    make_float2(0.0f, 0.0f);
            }
        }
    }
}

extern "C" void kernel_launch(void* const* d_in, const int* in_sizes, int n_in,
                              void* d_out, int out_size) {
    const float* X     = (const float*)d_in[0];
    const int*   types = (const int*)  d_in[1];
    const float* W0    = (const float*)d_in[2];
    const float* b0    = (const float*)d_in[3];
    const float* W1    = (const float*)d_in[4];
    const float* b1    = (const float*)d_in[5];
    float* out = (float*)d_out;

    // convert_x also zeroes g_cnt (stream order: completes before build_lists)
    convert_x_kernel<<<(MTOT * KDIM / 4) / 256, 256>>>(X);
    build_lists_kernel<<<MTOT / 256, 256>>>(types);
    {
        dim3 g(NDIM / 32, KDIM / 32, 2);
        dim3 b(32, 8);
        convert_w_kernel<<<g, b>>>(W0, W1);
    }

    cudaFuncSetAttribute(mot_gemm_mma, cudaFuncAttributeMaxDynamicSharedMemorySize, DYN_SMEM);
    dim3 grid((MTOT / BM) * (NDIM / BN), 1, 2);   // worst-case grid; tiles early-exit
    mot_gemm_mma<<<grid, 256, DYN_SMEM>>>(b0, b1, out);
}